// round 13
// baseline (speedup 1.0000x reference)
#include <cuda_runtime.h>
#include <cuda_fp16.h>
#include <cstdint>

// Problem constants
#define NROWS   500000
#define KCODES  512
#define DDIM    64
#define TILE_M  640
#define NTHREADS 640
#define NUMTILES ((NROWS + TILE_M - 1) / TILE_M)   // 782

// Shared memory layout (byte offsets into dynamic smem)
#define SMEM_B      0            // 512 x 128B fp16 (-2*e), SW128-swizzled
#define SMEM_ESQ    65536        // 512 floats (||e_k||^2)
#define SMEM_EMB    67584        // 512 x 256B fp32 embedding, XOR-swizzled rows
#define SMEM_IDX    198656       // 640 rows x 32B (4 lanes x int2 candidates)
#define SMEM_WIN    219136       // 640 int (winner per row)
#define SMEM_TOTAL  221696       // ~216.5 KB < 227 KB cap

__device__ __forceinline__ uint32_t smem_u32(const void* p) {
    uint32_t a;
    asm("{ .reg .u64 t; cvta.to.shared.u64 t, %1; cvt.u32.u64 %0, t; }" : "=r"(a) : "l"(p));
    return a;
}
__device__ __forceinline__ uint32_t swz(uint32_t bo) { return bo ^ ((bo >> 3) & 0x70); }
// fp32 emb row c, 16-byte chunk j (0..15): bank-decorrelated via XOR swizzle
__device__ __forceinline__ uint32_t embOff(int c, int j) {
    return (uint32_t)(SMEM_EMB + c * 256 + ((j * 16) ^ ((c & 7) << 4)));
}

__device__ __forceinline__ void mma_f16(float* d, const uint32_t* a, const uint32_t* b) {
    asm volatile(
        "mma.sync.aligned.m16n8k16.row.col.f32.f16.f16.f32 "
        "{%0,%1,%2,%3}, {%4,%5,%6,%7}, {%8,%9}, {%0,%1,%2,%3};"
        : "+f"(d[0]), "+f"(d[1]), "+f"(d[2]), "+f"(d[3])
        : "r"(a[0]), "r"(a[1]), "r"(a[2]), "r"(a[3]), "r"(b[0]), "r"(b[1]));
}
__device__ __forceinline__ void ldsm4(uint32_t* r, uint32_t addr) {
    asm volatile("ldmatrix.sync.aligned.m8n8.x4.shared.b16 {%0,%1,%2,%3}, [%4];"
        : "=r"(r[0]), "=r"(r[1]), "=r"(r[2]), "=r"(r[3]) : "r"(addr));
}
__device__ __forceinline__ uint32_t pack_h2(float2 v) {
    __half2 hh = __floats2half2_rn(v.x, v.y);
    return *reinterpret_cast<uint32_t*>(&hh);
}
// Pack 9-bit candidate index into score mantissa low bits (perturbation <= 2^-14 rel)
__device__ __forceinline__ float packIdx(float s, uint32_t idx) {
    return __uint_as_float((__float_as_uint(s) & 0xFFFFFE00u) | idx);
}

__global__ void __launch_bounds__(NTHREADS, 1) vq_kernel(
    const float* __restrict__ x, const float* __restrict__ emb,
    float* __restrict__ out, int out_size)
{
    extern __shared__ char smem[];
    const uint32_t sb = smem_u32(smem);
    const int tid  = threadIdx.x;
    const int lane = tid & 31;
    const int warpRow = (tid >> 5) * 32;     // 20 warps x 32 rows = 640 rows

    // ---- Stage B = fp16(-2e) SW128 + fp32 emb (swizzled) + exact e_sq ----
    if (tid < 512) {
        int r = tid;
        const float4* src = (const float4*)(emb + (size_t)r * DDIM);
        float ssum = 0.f;
#pragma unroll
        for (int j = 0; j < 16; j += 2) {
            float4 v0 = src[j], v1 = src[j + 1];
            ssum = fmaf(v0.x, v0.x, ssum); ssum = fmaf(v0.y, v0.y, ssum);
            ssum = fmaf(v0.z, v0.z, ssum); ssum = fmaf(v0.w, v0.w, ssum);
            ssum = fmaf(v1.x, v1.x, ssum); ssum = fmaf(v1.y, v1.y, ssum);
            ssum = fmaf(v1.z, v1.z, ssum); ssum = fmaf(v1.w, v1.w, ssum);
            *(float4*)(smem + embOff(r, j))     = v0;
            *(float4*)(smem + embOff(r, j + 1)) = v1;
            uint4 hi = make_uint4(
                pack_h2(make_float2(-2.f * v0.x, -2.f * v0.y)),
                pack_h2(make_float2(-2.f * v0.z, -2.f * v0.w)),
                pack_h2(make_float2(-2.f * v1.x, -2.f * v1.y)),
                pack_h2(make_float2(-2.f * v1.z, -2.f * v1.w)));
            uint32_t sw = swz((uint32_t)r * 128u + (uint32_t)(j >> 1) * 16u);
            *(uint4*)(smem + SMEM_B + sw) = hi;
        }
        ((float*)(smem + SMEM_ESQ))[r] = ssum;
    }
    __syncthreads();

    // ---- Per-lane constant B addressing (swizzle algebra hoisted) ----
    const int bRow4 = (lane & 7) + ((lane >> 4) << 3);
    const int bKb4  = ((lane >> 3) & 1) << 4;
    const uint32_t laneBaseB = (uint32_t)bRow4 * 128u + (uint32_t)(bKb4 ^ ((lane & 1) << 4));
    const uint32_t kXor = (uint32_t)(lane & 6) << 4;
    uint32_t bAddr[4];
#pragma unroll
    for (int ks = 0; ks < 4; ks++) {
        bAddr[ks] = sb + SMEM_B + laneBaseB + (((uint32_t)ks * 32u) ^ kXor);
    }

    const float* esq = (const float*)(smem + SMEM_ESQ);
    const int ciB = (lane & 3) * 2;

    for (int t = blockIdx.x; t < NUMTILES; t += gridDim.x) {
        const size_t base = (size_t)t * TILE_M;

        // ---- A fragments from global, fp16: 2 subtiles x 4 ks ----
        uint32_t ah[2][4][4];
        {
            const int kA = (lane & 3) * 2;
#pragma unroll
            for (int s = 0; s < 2; s++) {
                size_t r0 = base + warpRow + s * 16 + (lane >> 2);
                size_t r1 = r0 + 8;
                if (r0 >= NROWS) r0 = NROWS - 1;   // clamp: garbage rows never emitted
                if (r1 >= NROWS) r1 = NROWS - 1;
                const float* p0 = x + r0 * DDIM + kA;
                const float* p1 = x + r1 * DDIM + kA;
#pragma unroll
                for (int ks = 0; ks < 4; ks++) {
                    ah[s][ks][0] = pack_h2(*(const float2*)(p0 + ks * 16));
                    ah[s][ks][1] = pack_h2(*(const float2*)(p1 + ks * 16));
                    ah[s][ks][2] = pack_h2(*(const float2*)(p0 + ks * 16 + 8));
                    ah[s][ks][3] = pack_h2(*(const float2*)(p1 + ks * 16 + 8));
                }
            }
        }

        // ---- Packed top-2 trackers: k = s*2 + rowhalf -> 4 rows per lane ----
        float pb1[4], pb2[4];
#pragma unroll
        for (int k = 0; k < 4; k++) { pb1[k] = 3.4e38f; pb2[k] = 3.4e38f; }

        uint32_t nbOff = 0;
        uint32_t id0 = (uint32_t)ciB, id1 = id0 + 1, id2 = id0 + 8, id3 = id0 + 9;

#pragma unroll 1
        for (int np = 0; np < 32; np++) {
            const int nb = np * 16;
            float2 e01 = *(const float2*)(esq + nb + ciB);
            float2 e23 = *(const float2*)(esq + nb + 8 + ciB);
            float acc[2][2][4];
#pragma unroll
            for (int s = 0; s < 2; s++) {
                acc[s][0][0] = e01.x; acc[s][0][1] = e01.y;
                acc[s][0][2] = e01.x; acc[s][0][3] = e01.y;
                acc[s][1][0] = e23.x; acc[s][1][1] = e23.y;
                acc[s][1][2] = e23.x; acc[s][1][3] = e23.y;
            }

#pragma unroll
            for (int ks = 0; ks < 4; ks++) {
                uint32_t bh[4];
                ldsm4(bh, bAddr[ks] + nbOff);
#pragma unroll
                for (int s = 0; s < 2; s++) {
                    mma_f16(acc[s][0], ah[s][ks], bh);
                    mma_f16(acc[s][1], ah[s][ks], bh + 2);
                }
            }

            // ---- Epilogue: index-packed FMNMX network (no SEL/pred chains).
            //      Exact top-2-of-4 then sorted-pair merge, per row ----
#pragma unroll
            for (int s = 0; s < 2; s++) {
#pragma unroll
                for (int h = 0; h < 2; h++) {
                    const int k = s * 2 + h;
                    float f0 = packIdx(acc[s][0][h * 2],     id0);
                    float f1 = packIdx(acc[s][0][h * 2 + 1], id1);
                    float f2 = packIdx(acc[s][1][h * 2],     id2);
                    float f3 = packIdx(acc[s][1][h * 2 + 1], id3);
                    float lo1 = fminf(f0, f1), hi1 = fmaxf(f0, f1);
                    float lo2 = fminf(f2, f3), hi2 = fmaxf(f2, f3);
                    float m1 = fminf(lo1, lo2);
                    float m2 = fminf(fmaxf(lo1, lo2), fminf(hi1, hi2));
                    float tt = fmaxf(pb1[k], m1);
                    float uu = fminf(pb2[k], m2);
                    pb1[k] = fminf(pb1[k], m1);
                    pb2[k] = fminf(tt, uu);
                }
            }
            nbOff += 2048;
            id0 += 16; id1 += 16; id2 += 16; id3 += 16;
        }

        // ---- Write 2 candidates per (lane, row): 8 candidates per row ----
#pragma unroll
        for (int s = 0; s < 2; s++) {
#pragma unroll
            for (int h = 0; h < 2; h++) {
                const int k = s * 2 + h;
                int row = warpRow + s * 16 + h * 8 + (lane >> 2);
                int c1 = (int)(__float_as_uint(pb1[k]) & 0x1FFu);
                int c2 = (int)(__float_as_uint(pb2[k]) & 0x1FFu);
                *(int2*)(smem + SMEM_IDX + row * 32 + (lane & 3) * 8) = make_int2(c1, c2);
            }
        }
        __syncthreads();

        // ---- Exact fp32 rescore: 1 thread/row, all 8 candidates (emb smem) ----
        {
            const size_t g = base + tid;
            if (g < (size_t)NROWS) {
                const int4* cp = (const int4*)(smem + SMEM_IDX + tid * 32);
                int4 ca = cp[0], cb = cp[1];
                int c[8] = {ca.x, ca.y, ca.z, ca.w, cb.x, cb.y, cb.z, cb.w};
                uint32_t bas[8], xo[8];
#pragma unroll
                for (int i = 0; i < 8; i++) {
                    bas[i] = (uint32_t)(SMEM_EMB + c[i] * 256);
                    xo[i]  = (uint32_t)((c[i] & 7) << 4);
                }
                const float4* xr = (const float4*)(x + g * DDIM);
                float d[8] = {0.f, 0.f, 0.f, 0.f, 0.f, 0.f, 0.f, 0.f};
#pragma unroll
                for (int j = 0; j < 16; j++) {
                    float4 xv = xr[j];
                    uint32_t jj = (uint32_t)(j * 16);
#pragma unroll
                    for (int i = 0; i < 8; i++) {
                        float4 e = *(const float4*)(smem + bas[i] + (jj ^ xo[i]));
                        float u;
                        u = xv.x - e.x; d[i] = fmaf(u, u, d[i]);
                        u = xv.y - e.y; d[i] = fmaf(u, u, d[i]);
                        u = xv.z - e.z; d[i] = fmaf(u, u, d[i]);
                        u = xv.w - e.w; d[i] = fmaf(u, u, d[i]);
                    }
                }
                float dm = d[0]; int im = c[0];
#pragma unroll
                for (int i = 1; i < 8; i++) {
                    if (d[i] < dm || (d[i] == dm && c[i] < im)) { dm = d[i]; im = c[i]; }
                }
                ((int*)(smem + SMEM_WIN))[tid] = im;
                if (out_size >= NROWS * DDIM + NROWS) {
                    out[(size_t)NROWS * DDIM + g] = (float)im;
                }
            }
        }
        __syncthreads();

        // ---- Gather quantized rows from smem emb (8 threads/row, 32B each) ----
        if (out_size >= NROWS * DDIM) {
#pragma unroll
            for (int sweep = 0; sweep < 8; sweep++) {
                int r = sweep * 80 + (tid >> 3);
                size_t gr = base + r;
                if (gr < (size_t)NROWS) {
                    int w = ((const int*)(smem + SMEM_WIN))[r];
                    int jj = (tid & 7) * 2;
                    float4 v0 = *(const float4*)(smem + embOff(w, jj));
                    float4 v1 = *(const float4*)(smem + embOff(w, jj + 1));
                    float4* q = (float4*)(out + gr * DDIM) + jj;
                    q[0] = v0; q[1] = v1;
                }
            }
        }
        __syncthreads();   // protect IDX/WIN before next tile
    }
}

extern "C" void kernel_launch(void* const* d_in, const int* in_sizes, int n_in,
                              void* d_out, int out_size) {
    const float* x   = (const float*)d_in[0];
    const float* emb = (const float*)d_in[1];
    float* out = (float*)d_out;
    cudaFuncSetAttribute(vq_kernel, cudaFuncAttributeMaxDynamicSharedMemorySize, SMEM_TOTAL);
    vq_kernel<<<148, NTHREADS, SMEM_TOTAL>>>(x, emb, out, out_size);
}

// round 14
// speedup vs baseline: 1.2349x; 1.2349x over previous
#include <cuda_runtime.h>
#include <cuda_fp16.h>
#include <cstdint>

// Problem constants
#define NROWS   500000
#define KCODES  512
#define DDIM    64
#define TILE_M  384
#define NTHREADS 768
#define NUMTILES ((NROWS + TILE_M - 1) / TILE_M)   // 1303

// Shared memory layout (byte offsets into dynamic smem)
#define SMEM_B      0            // 512 x 128B fp16 (-2*e), SW128-swizzled
#define SMEM_ESQ    65536        // 512 floats (||e_k||^2)
#define SMEM_EMB    67584        // 512 x 256B fp32 embedding, XOR-swizzled rows
#define SMEM_IDX    198656       // 384 rows x 32B (4 lanes x int2 candidates)
#define SMEM_WIN    210944       // 384 int (winner per row)
#define SMEM_TOTAL  212480       // ~207.5 KB

__device__ __forceinline__ uint32_t smem_u32(const void* p) {
    uint32_t a;
    asm("{ .reg .u64 t; cvta.to.shared.u64 t, %1; cvt.u32.u64 %0, t; }" : "=r"(a) : "l"(p));
    return a;
}
__device__ __forceinline__ uint32_t swz(uint32_t bo) { return bo ^ ((bo >> 3) & 0x70); }
// fp32 emb row c, 16-byte chunk j (0..15): bank-decorrelated via XOR swizzle
__device__ __forceinline__ uint32_t embOff(int c, int j) {
    return (uint32_t)(SMEM_EMB + c * 256 + ((j * 16) ^ ((c & 7) << 4)));
}

__device__ __forceinline__ void mma_f16(float* d, const uint32_t* a, const uint32_t* b) {
    asm volatile(
        "mma.sync.aligned.m16n8k16.row.col.f32.f16.f16.f32 "
        "{%0,%1,%2,%3}, {%4,%5,%6,%7}, {%8,%9}, {%0,%1,%2,%3};"
        : "+f"(d[0]), "+f"(d[1]), "+f"(d[2]), "+f"(d[3])
        : "r"(a[0]), "r"(a[1]), "r"(a[2]), "r"(a[3]), "r"(b[0]), "r"(b[1]));
}
__device__ __forceinline__ void ldsm4(uint32_t* r, uint32_t addr) {
    asm volatile("ldmatrix.sync.aligned.m8n8.x4.shared.b16 {%0,%1,%2,%3}, [%4];"
        : "=r"(r[0]), "=r"(r[1]), "=r"(r[2]), "=r"(r[3]) : "r"(addr));
}
__device__ __forceinline__ uint32_t pack_h2(float2 v) {
    __half2 hh = __floats2half2_rn(v.x, v.y);
    return *reinterpret_cast<uint32_t*>(&hh);
}
// Pack 9-bit candidate index into score mantissa low bits (perturbation <= 2^-14 rel)
__device__ __forceinline__ float packIdx(float s, uint32_t idx) {
    return __uint_as_float((__float_as_uint(s) & 0xFFFFFE00u) | idx);
}

__global__ void __launch_bounds__(NTHREADS, 1) vq_kernel(
    const float* __restrict__ x, const float* __restrict__ emb,
    float* __restrict__ out, int out_size)
{
    extern __shared__ char smem[];
    const uint32_t sb = smem_u32(smem);
    const int tid  = threadIdx.x;
    const int lane = tid & 31;
    const int warpRow = (tid >> 5) * 16;     // 24 warps x 16 rows = 384 rows

    // ---- Stage B = fp16(-2e) SW128 + fp32 emb (swizzled) + exact e_sq ----
    if (tid < 512) {
        int r = tid;
        const float4* src = (const float4*)(emb + (size_t)r * DDIM);
        float ssum = 0.f;
#pragma unroll
        for (int j = 0; j < 16; j += 2) {
            float4 v0 = src[j], v1 = src[j + 1];
            ssum = fmaf(v0.x, v0.x, ssum); ssum = fmaf(v0.y, v0.y, ssum);
            ssum = fmaf(v0.z, v0.z, ssum); ssum = fmaf(v0.w, v0.w, ssum);
            ssum = fmaf(v1.x, v1.x, ssum); ssum = fmaf(v1.y, v1.y, ssum);
            ssum = fmaf(v1.z, v1.z, ssum); ssum = fmaf(v1.w, v1.w, ssum);
            *(float4*)(smem + embOff(r, j))     = v0;
            *(float4*)(smem + embOff(r, j + 1)) = v1;
            uint4 hi = make_uint4(
                pack_h2(make_float2(-2.f * v0.x, -2.f * v0.y)),
                pack_h2(make_float2(-2.f * v0.z, -2.f * v0.w)),
                pack_h2(make_float2(-2.f * v1.x, -2.f * v1.y)),
                pack_h2(make_float2(-2.f * v1.z, -2.f * v1.w)));
            uint32_t sw = swz((uint32_t)r * 128u + (uint32_t)(j >> 1) * 16u);
            *(uint4*)(smem + SMEM_B + sw) = hi;
        }
        ((float*)(smem + SMEM_ESQ))[r] = ssum;
    }
    __syncthreads();

    // ---- Per-lane constant B addressing (swizzle algebra hoisted) ----
    const int bRow4 = (lane & 7) + ((lane >> 4) << 3);
    const int bKb4  = ((lane >> 3) & 1) << 4;
    const uint32_t laneBaseB = (uint32_t)bRow4 * 128u + (uint32_t)(bKb4 ^ ((lane & 1) << 4));
    const uint32_t kXor = (uint32_t)(lane & 6) << 4;
    uint32_t bAddr[4];
#pragma unroll
    for (int ks = 0; ks < 4; ks++) {
        bAddr[ks] = sb + SMEM_B + laneBaseB + (((uint32_t)ks * 32u) ^ kXor);
    }

    const float* esq = (const float*)(smem + SMEM_ESQ);
    const int ciB = (lane & 3) * 2;

    for (int t = blockIdx.x; t < NUMTILES; t += gridDim.x) {
        const size_t base = (size_t)t * TILE_M;

        // ---- A fragments straight from global, fp16 ----
        uint32_t ah[4][4];
        {
            const int kA = (lane & 3) * 2;
            size_t r0 = base + warpRow + (lane >> 2);
            size_t r1 = r0 + 8;
            if (r0 >= NROWS) r0 = NROWS - 1;   // clamp: garbage rows never emitted
            if (r1 >= NROWS) r1 = NROWS - 1;
            const float* p0 = x + r0 * DDIM + kA;
            const float* p1 = x + r1 * DDIM + kA;
#pragma unroll
            for (int ks = 0; ks < 4; ks++) {
                ah[ks][0] = pack_h2(*(const float2*)(p0 + ks * 16));
                ah[ks][1] = pack_h2(*(const float2*)(p1 + ks * 16));
                ah[ks][2] = pack_h2(*(const float2*)(p0 + ks * 16 + 8));
                ah[ks][3] = pack_h2(*(const float2*)(p1 + ks * 16 + 8));
            }
        }

        // ---- Packed top-2 trackers per row-half ----
        float pb1[2], pb2[2];
#pragma unroll
        for (int k = 0; k < 2; k++) { pb1[k] = 3.4e38f; pb2[k] = 3.4e38f; }

        uint32_t nbOff = 0;
        uint32_t id0 = (uint32_t)ciB, id1 = id0 + 1, id2 = id0 + 8, id3 = id0 + 9;

#pragma unroll 1
        for (int np = 0; np < 32; np++) {
            const int nb = np * 16;
            float2 e01 = *(const float2*)(esq + nb + ciB);
            float2 e23 = *(const float2*)(esq + nb + 8 + ciB);
            float acc[2][4];
            acc[0][0] = e01.x; acc[0][1] = e01.y; acc[0][2] = e01.x; acc[0][3] = e01.y;
            acc[1][0] = e23.x; acc[1][1] = e23.y; acc[1][2] = e23.x; acc[1][3] = e23.y;

#pragma unroll
            for (int ks = 0; ks < 4; ks++) {
                uint32_t bh[4];
                ldsm4(bh, bAddr[ks] + nbOff);
                mma_f16(acc[0], ah[ks], bh);
                mma_f16(acc[1], ah[ks], bh + 2);
            }

            // ---- Epilogue: index-packed FMNMX network (validated in R13).
            //      Exact top-2-of-4 then sorted-pair merge, per row-half ----
#pragma unroll
            for (int h = 0; h < 2; h++) {
                float f0 = packIdx(acc[0][h * 2],     id0);
                float f1 = packIdx(acc[0][h * 2 + 1], id1);
                float f2 = packIdx(acc[1][h * 2],     id2);
                float f3 = packIdx(acc[1][h * 2 + 1], id3);
                float lo1 = fminf(f0, f1), hi1 = fmaxf(f0, f1);
                float lo2 = fminf(f2, f3), hi2 = fmaxf(f2, f3);
                float m1 = fminf(lo1, lo2);
                float m2 = fminf(fmaxf(lo1, lo2), fminf(hi1, hi2));
                float tt = fmaxf(pb1[h], m1);
                float uu = fminf(pb2[h], m2);
                pb1[h] = fminf(pb1[h], m1);
                pb2[h] = fminf(tt, uu);
            }
            nbOff += 2048;
            id0 += 16; id1 += 16; id2 += 16; id3 += 16;
        }

        // ---- Every thread writes its top-2 -> 8 candidates per row ----
#pragma unroll
        for (int tk = 0; tk < 2; tk++) {
            int row = warpRow + tk * 8 + (lane >> 2);
            int c1 = (int)(__float_as_uint(pb1[tk]) & 0x1FFu);
            int c2 = (int)(__float_as_uint(pb2[tk]) & 0x1FFu);
            *(int2*)(smem + SMEM_IDX + row * 32 + (lane & 3) * 8) = make_int2(c1, c2);
        }
        __syncthreads();

        // ---- Exact fp32 rescore of ALL 8 candidates (emb from smem) ----
        {
            const int row  = tid >> 1;
            const int half = tid & 1;
            const size_t g = base + row;
            if (g < (size_t)NROWS) {
                const int2* cp = (const int2*)(smem + SMEM_IDX + row * 32 + half * 16);
                int2 ca = cp[0], cb = cp[1];
                int c[4] = {ca.x, ca.y, cb.x, cb.y};
                const float4* xr = (const float4*)(x + g * DDIM);
                float d0 = 0.f, d1 = 0.f, d2 = 0.f, d3 = 0.f;
#pragma unroll
                for (int j = 0; j < 16; j++) {
                    float4 xv = xr[j];
                    float4 a  = *(const float4*)(smem + embOff(c[0], j));
                    float4 b  = *(const float4*)(smem + embOff(c[1], j));
                    float4 cc = *(const float4*)(smem + embOff(c[2], j));
                    float4 dd = *(const float4*)(smem + embOff(c[3], j));
                    float u;
                    u = xv.x - a.x;  d0 = fmaf(u, u, d0);
                    u = xv.y - a.y;  d0 = fmaf(u, u, d0);
                    u = xv.z - a.z;  d0 = fmaf(u, u, d0);
                    u = xv.w - a.w;  d0 = fmaf(u, u, d0);
                    u = xv.x - b.x;  d1 = fmaf(u, u, d1);
                    u = xv.y - b.y;  d1 = fmaf(u, u, d1);
                    u = xv.z - b.z;  d1 = fmaf(u, u, d1);
                    u = xv.w - b.w;  d1 = fmaf(u, u, d1);
                    u = xv.x - cc.x; d2 = fmaf(u, u, d2);
                    u = xv.y - cc.y; d2 = fmaf(u, u, d2);
                    u = xv.z - cc.z; d2 = fmaf(u, u, d2);
                    u = xv.w - cc.w; d2 = fmaf(u, u, d2);
                    u = xv.x - dd.x; d3 = fmaf(u, u, d3);
                    u = xv.y - dd.y; d3 = fmaf(u, u, d3);
                    u = xv.z - dd.z; d3 = fmaf(u, u, d3);
                    u = xv.w - dd.w; d3 = fmaf(u, u, d3);
                }
                float dm = d0; int im = c[0];
                if (d1 < dm || (d1 == dm && c[1] < im)) { dm = d1; im = c[1]; }
                if (d2 < dm || (d2 == dm && c[2] < im)) { dm = d2; im = c[2]; }
                if (d3 < dm || (d3 == dm && c[3] < im)) { dm = d3; im = c[3]; }
                float do_ = __shfl_xor_sync(0xFFFFFFFFu, dm, 1);
                int   io_ = __shfl_xor_sync(0xFFFFFFFFu, im, 1);
                if (half == 0) {
                    int win = (do_ < dm || (do_ == dm && io_ < im)) ? io_ : im;
                    ((int*)(smem + SMEM_WIN))[row] = win;
                    if (out_size >= NROWS * DDIM + NROWS) {
                        out[(size_t)NROWS * DDIM + g] = (float)win;
                    }
                }
            }
        }
        __syncthreads();

        // ---- Gather quantized rows from smem emb (8 threads/row, 32B each) ----
        if (out_size >= NROWS * DDIM) {
#pragma unroll
            for (int sweep = 0; sweep < 4; sweep++) {
                int r = sweep * 96 + (tid >> 3);
                size_t gr = base + r;
                if (r < TILE_M && gr < (size_t)NROWS) {
                    int w = ((const int*)(smem + SMEM_WIN))[r];
                    int jj = (tid & 7) * 2;
                    float4 v0 = *(const float4*)(smem + embOff(w, jj));
                    float4 v1 = *(const float4*)(smem + embOff(w, jj + 1));
                    float4* q = (float4*)(out + gr * DDIM) + jj;
                    q[0] = v0; q[1] = v1;
                }
            }
        }
        __syncthreads();   // protect IDX/WIN before next tile
    }
}

extern "C" void kernel_launch(void* const* d_in, const int* in_sizes, int n_in,
                              void* d_out, int out_size) {
    const float* x   = (const float*)d_in[0];
    const float* emb = (const float*)d_in[1];
    float* out = (float*)d_out;
    cudaFuncSetAttribute(vq_kernel, cudaFuncAttributeMaxDynamicSharedMemorySize, SMEM_TOTAL);
    vq_kernel<<<148, NTHREADS, SMEM_TOTAL>>>(x, emb, out, out_size);
}

// round 15
// speedup vs baseline: 1.3628x; 1.1036x over previous
#include <cuda_runtime.h>
#include <cuda_fp16.h>
#include <cstdint>

// Problem constants
#define NROWS   500000
#define KCODES  512
#define DDIM    64
#define TILE_M  384
#define NTHREADS 768
#define NUMTILES ((NROWS + TILE_M - 1) / TILE_M)   // 1303
#define MARGIN  0.15f

// Shared memory layout (byte offsets into dynamic smem)
#define SMEM_B      0            // 512 x 128B fp16 (-2*e), SW128-swizzled
#define SMEM_ESQ    65536        // 512 floats (||e_k||^2)
#define SMEM_EMB    67584        // 512 x 256B fp32 embedding, XOR-swizzled rows
#define SMEM_IDX    198656       // 384 rows x 32B (4 lanes x float2 packed cands)
#define SMEM_WIN    210944       // 384 int (winner per row)
#define SMEM_TOTAL  212480       // ~207.5 KB

__device__ __forceinline__ uint32_t smem_u32(const void* p) {
    uint32_t a;
    asm("{ .reg .u64 t; cvta.to.shared.u64 t, %1; cvt.u32.u64 %0, t; }" : "=r"(a) : "l"(p));
    return a;
}
__device__ __forceinline__ uint32_t swz(uint32_t bo) { return bo ^ ((bo >> 3) & 0x70); }
// fp32 emb row c, 16-byte chunk j (0..15): bank-decorrelated via XOR swizzle
__device__ __forceinline__ uint32_t embOff(int c, int j) {
    return (uint32_t)(SMEM_EMB + c * 256 + ((j * 16) ^ ((c & 7) << 4)));
}

__device__ __forceinline__ void mma_f16(float* d, const uint32_t* a, const uint32_t* b) {
    asm volatile(
        "mma.sync.aligned.m16n8k16.row.col.f32.f16.f16.f32 "
        "{%0,%1,%2,%3}, {%4,%5,%6,%7}, {%8,%9}, {%0,%1,%2,%3};"
        : "+f"(d[0]), "+f"(d[1]), "+f"(d[2]), "+f"(d[3])
        : "r"(a[0]), "r"(a[1]), "r"(a[2]), "r"(a[3]), "r"(b[0]), "r"(b[1]));
}
__device__ __forceinline__ void ldsm4(uint32_t* r, uint32_t addr) {
    asm volatile("ldmatrix.sync.aligned.m8n8.x4.shared.b16 {%0,%1,%2,%3}, [%4];"
        : "=r"(r[0]), "=r"(r[1]), "=r"(r[2]), "=r"(r[3]) : "r"(addr));
}
__device__ __forceinline__ uint32_t pack_h2(float2 v) {
    __half2 hh = __floats2half2_rn(v.x, v.y);
    return *reinterpret_cast<uint32_t*>(&hh);
}
// Pack 9-bit candidate index into score mantissa low bits (perturbation <= 2^-14 rel)
__device__ __forceinline__ float packIdx(float s, uint32_t idx) {
    return __uint_as_float((__float_as_uint(s) & 0xFFFFFE00u) | idx);
}

__global__ void __launch_bounds__(NTHREADS, 1) vq_kernel(
    const float* __restrict__ x, const float* __restrict__ emb,
    float* __restrict__ out, int out_size)
{
    extern __shared__ char smem[];
    const uint32_t sb = smem_u32(smem);
    const int tid  = threadIdx.x;
    const int lane = tid & 31;
    const int warpRow = (tid >> 5) * 16;     // 24 warps x 16 rows = 384 rows

    // ---- Stage B = fp16(-2e) SW128 + fp32 emb (swizzled) + exact e_sq ----
    if (tid < 512) {
        int r = tid;
        const float4* src = (const float4*)(emb + (size_t)r * DDIM);
        float ssum = 0.f;
#pragma unroll
        for (int j = 0; j < 16; j += 2) {
            float4 v0 = src[j], v1 = src[j + 1];
            ssum = fmaf(v0.x, v0.x, ssum); ssum = fmaf(v0.y, v0.y, ssum);
            ssum = fmaf(v0.z, v0.z, ssum); ssum = fmaf(v0.w, v0.w, ssum);
            ssum = fmaf(v1.x, v1.x, ssum); ssum = fmaf(v1.y, v1.y, ssum);
            ssum = fmaf(v1.z, v1.z, ssum); ssum = fmaf(v1.w, v1.w, ssum);
            *(float4*)(smem + embOff(r, j))     = v0;
            *(float4*)(smem + embOff(r, j + 1)) = v1;
            uint4 hi = make_uint4(
                pack_h2(make_float2(-2.f * v0.x, -2.f * v0.y)),
                pack_h2(make_float2(-2.f * v0.z, -2.f * v0.w)),
                pack_h2(make_float2(-2.f * v1.x, -2.f * v1.y)),
                pack_h2(make_float2(-2.f * v1.z, -2.f * v1.w)));
            uint32_t sw = swz((uint32_t)r * 128u + (uint32_t)(j >> 1) * 16u);
            *(uint4*)(smem + SMEM_B + sw) = hi;
        }
        ((float*)(smem + SMEM_ESQ))[r] = ssum;
    }
    __syncthreads();

    // ---- Per-lane constant B addressing (swizzle algebra hoisted) ----
    const int bRow4 = (lane & 7) + ((lane >> 4) << 3);
    const int bKb4  = ((lane >> 3) & 1) << 4;
    const uint32_t laneBaseB = (uint32_t)bRow4 * 128u + (uint32_t)(bKb4 ^ ((lane & 1) << 4));
    const uint32_t kXor = (uint32_t)(lane & 6) << 4;
    uint32_t bAddr[4];
#pragma unroll
    for (int ks = 0; ks < 4; ks++) {
        bAddr[ks] = sb + SMEM_B + laneBaseB + (((uint32_t)ks * 32u) ^ kXor);
    }

    const float* esq = (const float*)(smem + SMEM_ESQ);
    const int ciB = (lane & 3) * 2;

    for (int t = blockIdx.x; t < NUMTILES; t += gridDim.x) {
        const size_t base = (size_t)t * TILE_M;

        // ---- A fragments straight from global, fp16 ----
        uint32_t ah[4][4];
        {
            const int kA = (lane & 3) * 2;
            size_t r0 = base + warpRow + (lane >> 2);
            size_t r1 = r0 + 8;
            if (r0 >= NROWS) r0 = NROWS - 1;   // clamp: garbage rows never emitted
            if (r1 >= NROWS) r1 = NROWS - 1;
            const float* p0 = x + r0 * DDIM + kA;
            const float* p1 = x + r1 * DDIM + kA;
#pragma unroll
            for (int ks = 0; ks < 4; ks++) {
                ah[ks][0] = pack_h2(*(const float2*)(p0 + ks * 16));
                ah[ks][1] = pack_h2(*(const float2*)(p1 + ks * 16));
                ah[ks][2] = pack_h2(*(const float2*)(p0 + ks * 16 + 8));
                ah[ks][3] = pack_h2(*(const float2*)(p1 + ks * 16 + 8));
            }
        }

        // ---- Packed top-2 trackers per row-half ----
        float pb1[2], pb2[2];
#pragma unroll
        for (int k = 0; k < 2; k++) { pb1[k] = 3.4e38f; pb2[k] = 3.4e38f; }

        uint32_t nbOff = 0;
        uint32_t id0 = (uint32_t)ciB, id1 = id0 + 1, id2 = id0 + 8, id3 = id0 + 9;

#pragma unroll 1
        for (int np = 0; np < 32; np++) {
            const int nb = np * 16;
            float2 e01 = *(const float2*)(esq + nb + ciB);
            float2 e23 = *(const float2*)(esq + nb + 8 + ciB);
            float acc[2][4];
            acc[0][0] = e01.x; acc[0][1] = e01.y; acc[0][2] = e01.x; acc[0][3] = e01.y;
            acc[1][0] = e23.x; acc[1][1] = e23.y; acc[1][2] = e23.x; acc[1][3] = e23.y;

#pragma unroll
            for (int ks = 0; ks < 4; ks++) {
                uint32_t bh[4];
                ldsm4(bh, bAddr[ks] + nbOff);
                mma_f16(acc[0], ah[ks], bh);
                mma_f16(acc[1], ah[ks], bh + 2);
            }

            // ---- Epilogue: index-packed FMNMX network (validated R13/R14) ----
#pragma unroll
            for (int h = 0; h < 2; h++) {
                float f0 = packIdx(acc[0][h * 2],     id0);
                float f1 = packIdx(acc[0][h * 2 + 1], id1);
                float f2 = packIdx(acc[1][h * 2],     id2);
                float f3 = packIdx(acc[1][h * 2 + 1], id3);
                float lo1 = fminf(f0, f1), hi1 = fmaxf(f0, f1);
                float lo2 = fminf(f2, f3), hi2 = fmaxf(f2, f3);
                float m1 = fminf(lo1, lo2);
                float m2 = fminf(fmaxf(lo1, lo2), fminf(hi1, hi2));
                float tt = fmaxf(pb1[h], m1);
                float uu = fminf(pb2[h], m2);
                pb1[h] = fminf(pb1[h], m1);
                pb2[h] = fminf(tt, uu);
            }
            nbOff += 2048;
            id0 += 16; id1 += 16; id2 += 16; id3 += 16;
        }

        // ---- Every thread writes packed top-2 -> 8 packed cands per row ----
#pragma unroll
        for (int tk = 0; tk < 2; tk++) {
            int row = warpRow + tk * 8 + (lane >> 2);
            *(float2*)(smem + SMEM_IDX + row * 32 + (lane & 3) * 8) =
                make_float2(pb1[tk], pb2[tk]);
        }
        __syncthreads();

        // ---- Margin-gated winner: fast path = approx argmin of 8; slow path
        //      (close 2nd) = exact fp32 rescore of all 8 (emb from smem) ----
        if (tid < TILE_M) {
            const size_t g = base + tid;
            if (g < (size_t)NROWS) {
                float4 pa = *(const float4*)(smem + SMEM_IDX + tid * 32);
                float4 pb = *(const float4*)(smem + SMEM_IDX + tid * 32 + 16);
                // top-2 of 8 via FMNMX network
                float loA = fminf(pa.x, pa.y), hiA = fmaxf(pa.x, pa.y);
                float loB = fminf(pa.z, pa.w), hiB = fmaxf(pa.z, pa.w);
                float loC = fminf(pb.x, pb.y), hiC = fmaxf(pb.x, pb.y);
                float loD = fminf(pb.z, pb.w), hiD = fmaxf(pb.z, pb.w);
                float mAB = fminf(loA, loB);
                float sAB = fminf(fmaxf(loA, loB), fminf(hiA, hiB));
                float mCD = fminf(loC, loD);
                float sCD = fminf(fmaxf(loC, loD), fminf(hiC, hiD));
                float m1 = fminf(mAB, mCD);
                float m2 = fminf(fmaxf(mAB, mCD), fminf(sAB, sCD));
                int win = (int)(__float_as_uint(m1) & 0x1FFu);
                if (m2 - m1 <= MARGIN) {
                    // Slow path: exact rescore of all 8 candidates, pairwise.
                    float v[8] = {pa.x, pa.y, pa.z, pa.w, pb.x, pb.y, pb.z, pb.w};
                    const float4* xr = (const float4*)(x + g * DDIM);
                    float best = 3.4e38f; int bidx = 0x7FFFFFFF;
#pragma unroll
                    for (int p = 0; p < 4; p++) {
                        int ca = (int)(__float_as_uint(v[2*p])     & 0x1FFu);
                        int cb = (int)(__float_as_uint(v[2*p + 1]) & 0x1FFu);
                        uint32_t baA = (uint32_t)(SMEM_EMB + ca * 256);
                        uint32_t baB = (uint32_t)(SMEM_EMB + cb * 256);
                        uint32_t xoA = (uint32_t)((ca & 7) << 4);
                        uint32_t xoB = (uint32_t)((cb & 7) << 4);
                        float da = 0.f, db = 0.f;
#pragma unroll
                        for (int j = 0; j < 16; j++) {
                            float4 xv = xr[j];
                            uint32_t jj = (uint32_t)(j * 16);
                            float4 ea = *(const float4*)(smem + baA + (jj ^ xoA));
                            float4 eb = *(const float4*)(smem + baB + (jj ^ xoB));
                            float u;
                            u = xv.x - ea.x; da = fmaf(u, u, da);
                            u = xv.y - ea.y; da = fmaf(u, u, da);
                            u = xv.z - ea.z; da = fmaf(u, u, da);
                            u = xv.w - ea.w; da = fmaf(u, u, da);
                            u = xv.x - eb.x; db = fmaf(u, u, db);
                            u = xv.y - eb.y; db = fmaf(u, u, db);
                            u = xv.z - eb.z; db = fmaf(u, u, db);
                            u = xv.w - eb.w; db = fmaf(u, u, db);
                        }
                        if (da < best || (da == best && ca < bidx)) { best = da; bidx = ca; }
                        if (db < best || (db == best && cb < bidx)) { best = db; bidx = cb; }
                    }
                    win = bidx;
                }
                ((int*)(smem + SMEM_WIN))[tid] = win;
                if (out_size >= NROWS * DDIM + NROWS) {
                    out[(size_t)NROWS * DDIM + g] = (float)win;
                }
            }
        }
        __syncthreads();

        // ---- Gather quantized rows from smem emb (8 threads/row, 32B each) ----
        if (out_size >= NROWS * DDIM) {
#pragma unroll
            for (int sweep = 0; sweep < 4; sweep++) {
                int r = sweep * 96 + (tid >> 3);
                size_t gr = base + r;
                if (r < TILE_M && gr < (size_t)NROWS) {
                    int w = ((const int*)(smem + SMEM_WIN))[r];
                    int jj = (tid & 7) * 2;
                    float4 v0 = *(const float4*)(smem + embOff(w, jj));
                    float4 v1 = *(const float4*)(smem + embOff(w, jj + 1));
                    float4* q = (float4*)(out + gr * DDIM) + jj;
                    q[0] = v0; q[1] = v1;
                }
            }
        }
        __syncthreads();   // protect IDX/WIN before next tile
    }
}

extern "C" void kernel_launch(void* const* d_in, const int* in_sizes, int n_in,
                              void* d_out, int out_size) {
    const float* x   = (const float*)d_in[0];
    const float* emb = (const float*)d_in[1];
    float* out = (float*)d_out;
    cudaFuncSetAttribute(vq_kernel, cudaFuncAttributeMaxDynamicSharedMemorySize, SMEM_TOTAL);
    vq_kernel<<<148, NTHREADS, SMEM_TOTAL>>>(x, emb, out, out_size);
}

// round 16
// speedup vs baseline: 1.8589x; 1.3640x over previous
#include <cuda_runtime.h>
#include <cuda_fp16.h>
#include <cstdint>

// Problem constants
#define NROWS   500000
#define KCODES  512
#define DDIM    64
#define TILE_M  384
#define NTHREADS 768
#define NUMTILES ((NROWS + TILE_M - 1) / TILE_M)   // 1303
#define MARGIN  0.15f

// Shared memory layout (byte offsets into dynamic smem)
#define SMEM_B      0            // 512 x 128B fp16 (-2*e), SW128-swizzled
#define SMEM_ESQ    65536        // 512 floats (||e_k||^2)
#define SMEM_EMB    67584        // 512 x 256B fp32 embedding, XOR-swizzled rows
#define SMEM_IDX    198656       // 384 rows x 32B (4 lanes x float2 packed cands)
#define SMEM_WIN    210944       // 384 int (winner per row)
#define SMEM_TOTAL  212480       // ~207.5 KB

__device__ __forceinline__ uint32_t smem_u32(const void* p) {
    uint32_t a;
    asm("{ .reg .u64 t; cvta.to.shared.u64 t, %1; cvt.u32.u64 %0, t; }" : "=r"(a) : "l"(p));
    return a;
}
__device__ __forceinline__ uint32_t swz(uint32_t bo) { return bo ^ ((bo >> 3) & 0x70); }
// fp32 emb row c, 16-byte chunk j (0..15): bank-decorrelated via XOR swizzle
__device__ __forceinline__ uint32_t embOff(int c, int j) {
    return (uint32_t)(SMEM_EMB + c * 256 + ((j * 16) ^ ((c & 7) << 4)));
}

__device__ __forceinline__ void mma_f16(float* d, const uint32_t* a, const uint32_t* b) {
    asm volatile(
        "mma.sync.aligned.m16n8k16.row.col.f32.f16.f16.f32 "
        "{%0,%1,%2,%3}, {%4,%5,%6,%7}, {%8,%9}, {%0,%1,%2,%3};"
        : "+f"(d[0]), "+f"(d[1]), "+f"(d[2]), "+f"(d[3])
        : "r"(a[0]), "r"(a[1]), "r"(a[2]), "r"(a[3]), "r"(b[0]), "r"(b[1]));
}
__device__ __forceinline__ void ldsm4(uint32_t* r, uint32_t addr) {
    asm volatile("ldmatrix.sync.aligned.m8n8.x4.shared.b16 {%0,%1,%2,%3}, [%4];"
        : "=r"(r[0]), "=r"(r[1]), "=r"(r[2]), "=r"(r[3]) : "r"(addr));
}
__device__ __forceinline__ uint32_t pack_h2(float2 v) {
    __half2 hh = __floats2half2_rn(v.x, v.y);
    return *reinterpret_cast<uint32_t*>(&hh);
}
// Pack 9-bit candidate index into score mantissa low bits (perturbation <= 2^-14 rel)
__device__ __forceinline__ float packIdx(float s, uint32_t idx) {
    return __uint_as_float((__float_as_uint(s) & 0xFFFFFE00u) | idx);
}

__global__ void __launch_bounds__(NTHREADS, 1) vq_kernel(
    const float* __restrict__ x, const float* __restrict__ emb,
    float* __restrict__ out, int out_size)
{
    extern __shared__ char smem[];
    const uint32_t sb = smem_u32(smem);
    const int tid  = threadIdx.x;
    const int lane = tid & 31;
    const int warpRow = (tid >> 5) * 16;     // 24 warps x 16 rows = 384 rows

    // ---- Stage B = fp16(-2e) SW128 + fp32 emb (swizzled) + exact e_sq ----
    if (tid < 512) {
        int r = tid;
        const float4* src = (const float4*)(emb + (size_t)r * DDIM);
        float ssum = 0.f;
#pragma unroll
        for (int j = 0; j < 16; j += 2) {
            float4 v0 = src[j], v1 = src[j + 1];
            ssum = fmaf(v0.x, v0.x, ssum); ssum = fmaf(v0.y, v0.y, ssum);
            ssum = fmaf(v0.z, v0.z, ssum); ssum = fmaf(v0.w, v0.w, ssum);
            ssum = fmaf(v1.x, v1.x, ssum); ssum = fmaf(v1.y, v1.y, ssum);
            ssum = fmaf(v1.z, v1.z, ssum); ssum = fmaf(v1.w, v1.w, ssum);
            *(float4*)(smem + embOff(r, j))     = v0;
            *(float4*)(smem + embOff(r, j + 1)) = v1;
            uint4 hi = make_uint4(
                pack_h2(make_float2(-2.f * v0.x, -2.f * v0.y)),
                pack_h2(make_float2(-2.f * v0.z, -2.f * v0.w)),
                pack_h2(make_float2(-2.f * v1.x, -2.f * v1.y)),
                pack_h2(make_float2(-2.f * v1.z, -2.f * v1.w)));
            uint32_t sw = swz((uint32_t)r * 128u + (uint32_t)(j >> 1) * 16u);
            *(uint4*)(smem + SMEM_B + sw) = hi;
        }
        ((float*)(smem + SMEM_ESQ))[r] = ssum;
    }
    __syncthreads();

    // ---- Per-lane constant B addressing (swizzle algebra hoisted) ----
    const int bRow4 = (lane & 7) + ((lane >> 4) << 3);
    const int bKb4  = ((lane >> 3) & 1) << 4;
    const uint32_t laneBaseB = (uint32_t)bRow4 * 128u + (uint32_t)(bKb4 ^ ((lane & 1) << 4));
    const uint32_t kXor = (uint32_t)(lane & 6) << 4;
    uint32_t bAddr[4];
#pragma unroll
    for (int ks = 0; ks < 4; ks++) {
        bAddr[ks] = sb + SMEM_B + laneBaseB + (((uint32_t)ks * 32u) ^ kXor);
    }

    const float* esq = (const float*)(smem + SMEM_ESQ);
    const int ciB = (lane & 3) * 2;

    for (int t = blockIdx.x; t < NUMTILES; t += gridDim.x) {
        const size_t base = (size_t)t * TILE_M;

        // ---- A fragments straight from global, fp16 ----
        uint32_t ah[4][4];
        {
            const int kA = (lane & 3) * 2;
            size_t r0 = base + warpRow + (lane >> 2);
            size_t r1 = r0 + 8;
            if (r0 >= NROWS) r0 = NROWS - 1;   // clamp: garbage rows never emitted
            if (r1 >= NROWS) r1 = NROWS - 1;
            const float* p0 = x + r0 * DDIM + kA;
            const float* p1 = x + r1 * DDIM + kA;
#pragma unroll
            for (int ks = 0; ks < 4; ks++) {
                ah[ks][0] = pack_h2(*(const float2*)(p0 + ks * 16));
                ah[ks][1] = pack_h2(*(const float2*)(p1 + ks * 16));
                ah[ks][2] = pack_h2(*(const float2*)(p0 + ks * 16 + 8));
                ah[ks][3] = pack_h2(*(const float2*)(p1 + ks * 16 + 8));
            }
        }

        // ---- Packed top-2 trackers per row-half ----
        float pb1[2], pb2[2];
#pragma unroll
        for (int k = 0; k < 2; k++) { pb1[k] = 3.4e38f; pb2[k] = 3.4e38f; }

        uint32_t nbOff = 0;
        uint32_t id0 = (uint32_t)ciB, id1 = id0 + 1, id2 = id0 + 8, id3 = id0 + 9;

#pragma unroll 1
        for (int np = 0; np < 32; np++) {
            const int nb = np * 16;
            float2 e01 = *(const float2*)(esq + nb + ciB);
            float2 e23 = *(const float2*)(esq + nb + 8 + ciB);
            float acc[2][4];
            acc[0][0] = e01.x; acc[0][1] = e01.y; acc[0][2] = e01.x; acc[0][3] = e01.y;
            acc[1][0] = e23.x; acc[1][1] = e23.y; acc[1][2] = e23.x; acc[1][3] = e23.y;

#pragma unroll
            for (int ks = 0; ks < 4; ks++) {
                uint32_t bh[4];
                ldsm4(bh, bAddr[ks] + nbOff);
                mma_f16(acc[0], ah[ks], bh);
                mma_f16(acc[1], ah[ks], bh + 2);
            }

            // ---- Epilogue: index-packed FMNMX network (validated R13/R14) ----
#pragma unroll
            for (int h = 0; h < 2; h++) {
                float f0 = packIdx(acc[0][h * 2],     id0);
                float f1 = packIdx(acc[0][h * 2 + 1], id1);
                float f2 = packIdx(acc[1][h * 2],     id2);
                float f3 = packIdx(acc[1][h * 2 + 1], id3);
                float lo1 = fminf(f0, f1), hi1 = fmaxf(f0, f1);
                float lo2 = fminf(f2, f3), hi2 = fmaxf(f2, f3);
                float m1 = fminf(lo1, lo2);
                float m2 = fminf(fmaxf(lo1, lo2), fminf(hi1, hi2));
                float tt = fmaxf(pb1[h], m1);
                float uu = fminf(pb2[h], m2);
                pb1[h] = fminf(pb1[h], m1);
                pb2[h] = fminf(tt, uu);
            }
            nbOff += 2048;
            id0 += 16; id1 += 16; id2 += 16; id3 += 16;
        }

        // ---- Every thread writes packed top-2 -> 8 packed cands per row ----
#pragma unroll
        for (int tk = 0; tk < 2; tk++) {
            int row = warpRow + tk * 8 + (lane >> 2);
            *(float2*)(smem + SMEM_IDX + row * 32 + (lane & 3) * 8) =
                make_float2(pb1[tk], pb2[tk]);
        }
        __syncthreads();

        // ---- Margin-gated winner: fast path = approx argmin of 8; slow path
        //      rescored ONLY for candidates within MARGIN of the approx best
        //      (approx_i > m1 + 2*delta cannot win exactly; MARGIN = 2*delta) ----
        if (tid < TILE_M) {
            const size_t g = base + tid;
            if (g < (size_t)NROWS) {
                float4 pa = *(const float4*)(smem + SMEM_IDX + tid * 32);
                float4 pb = *(const float4*)(smem + SMEM_IDX + tid * 32 + 16);
                // top-2 of 8 via FMNMX network
                float loA = fminf(pa.x, pa.y), hiA = fmaxf(pa.x, pa.y);
                float loB = fminf(pa.z, pa.w), hiB = fmaxf(pa.z, pa.w);
                float loC = fminf(pb.x, pb.y), hiC = fmaxf(pb.x, pb.y);
                float loD = fminf(pb.z, pb.w), hiD = fmaxf(pb.z, pb.w);
                float mAB = fminf(loA, loB);
                float sAB = fminf(fmaxf(loA, loB), fminf(hiA, hiB));
                float mCD = fminf(loC, loD);
                float sCD = fminf(fmaxf(loC, loD), fminf(hiC, hiD));
                float m1 = fminf(mAB, mCD);
                float m2 = fminf(fmaxf(mAB, mCD), fminf(sAB, sCD));
                int win = (int)(__float_as_uint(m1) & 0x1FFu);
                if (m2 - m1 <= MARGIN) {
                    // Slow path: exact fp32 rescore of candidates within margin.
                    float v[8] = {pa.x, pa.y, pa.z, pa.w, pb.x, pb.y, pb.z, pb.w};
                    const float thr = m1 + MARGIN;
                    const float4* xr = (const float4*)(x + g * DDIM);
                    float best = 3.4e38f; int bidx = 0x7FFFFFFF;
#pragma unroll 1
                    for (int i = 0; i < 8; i++) {
                        if (v[i] > thr) continue;
                        int c = (int)(__float_as_uint(v[i]) & 0x1FFu);
                        uint32_t ba = (uint32_t)(SMEM_EMB + c * 256);
                        uint32_t xo = (uint32_t)((c & 7) << 4);
                        float d = 0.f;
#pragma unroll
                        for (int j = 0; j < 16; j++) {
                            float4 xv = xr[j];
                            float4 e = *(const float4*)(smem + ba + (((uint32_t)(j * 16)) ^ xo));
                            float u;
                            u = xv.x - e.x; d = fmaf(u, u, d);
                            u = xv.y - e.y; d = fmaf(u, u, d);
                            u = xv.z - e.z; d = fmaf(u, u, d);
                            u = xv.w - e.w; d = fmaf(u, u, d);
                        }
                        if (d < best || (d == best && c < bidx)) { best = d; bidx = c; }
                    }
                    win = bidx;
                }
                ((int*)(smem + SMEM_WIN))[tid] = win;
                if (out_size >= NROWS * DDIM + NROWS) {
                    out[(size_t)NROWS * DDIM + g] = (float)win;
                }
            }
        }
        __syncthreads();

        // ---- Gather quantized rows from smem emb (8 threads/row, 32B each) ----
        if (out_size >= NROWS * DDIM) {
#pragma unroll
            for (int sweep = 0; sweep < 4; sweep++) {
                int r = sweep * 96 + (tid >> 3);
                size_t gr = base + r;
                if (r < TILE_M && gr < (size_t)NROWS) {
                    int w = ((const int*)(smem + SMEM_WIN))[r];
                    int jj = (tid & 7) * 2;
                    float4 v0 = *(const float4*)(smem + embOff(w, jj));
                    float4 v1 = *(const float4*)(smem + embOff(w, jj + 1));
                    float4* q = (float4*)(out + gr * DDIM) + jj;
                    q[0] = v0; q[1] = v1;
                }
            }
        }
        __syncthreads();   // protect IDX/WIN before next tile
    }
}

extern "C" void kernel_launch(void* const* d_in, const int* in_sizes, int n_in,
                              void* d_out, int out_size) {
    const float* x   = (const float*)d_in[0];
    const float* emb = (const float*)d_in[1];
    float* out = (float*)d_out;
    cudaFuncSetAttribute(vq_kernel, cudaFuncAttributeMaxDynamicSharedMemorySize, SMEM_TOTAL);
    vq_kernel<<<148, NTHREADS, SMEM_TOTAL>>>(x, emb, out, out_size);
}

// round 17
// speedup vs baseline: 2.3896x; 1.2855x over previous
#include <cuda_runtime.h>
#include <cuda_fp16.h>
#include <cstdint>

// Problem constants
#define NROWS   500000
#define KCODES  512
#define DDIM    64
#define NTHREADS 768
#define NWARPS_BLK (NTHREADS / 32)            // 24
#define NBLOCKS 148
#define NWARPS_TOT (NBLOCKS * NWARPS_BLK)     // 3552
#define NCHUNKS (NROWS / 16)                  // 31250 (exact)
#define MARGIN  0.15f

// Shared memory layout (byte offsets into dynamic smem)
#define SMEM_B      0            // 512 x 128B fp16 (-2*e), SW128-swizzled
#define SMEM_ESQ    65536        // 512 floats (||e_k||^2)
#define SMEM_EMB    67584        // 512 x 256B fp32 embedding, XOR-swizzled rows
#define SMEM_IDX    198656       // 24 warps x 16 rows x 32B private scratch
#define SMEM_TOTAL  210944       // ~206 KB

__device__ __forceinline__ uint32_t smem_u32(const void* p) {
    uint32_t a;
    asm("{ .reg .u64 t; cvta.to.shared.u64 t, %1; cvt.u32.u64 %0, t; }" : "=r"(a) : "l"(p));
    return a;
}
__device__ __forceinline__ uint32_t swz(uint32_t bo) { return bo ^ ((bo >> 3) & 0x70); }
// fp32 emb row c, 16-byte chunk j (0..15): bank-decorrelated via XOR swizzle
__device__ __forceinline__ uint32_t embOff(int c, int j) {
    return (uint32_t)(SMEM_EMB + c * 256 + ((j * 16) ^ ((c & 7) << 4)));
}

__device__ __forceinline__ void mma_f16(float* d, const uint32_t* a, const uint32_t* b) {
    asm volatile(
        "mma.sync.aligned.m16n8k16.row.col.f32.f16.f16.f32 "
        "{%0,%1,%2,%3}, {%4,%5,%6,%7}, {%8,%9}, {%0,%1,%2,%3};"
        : "+f"(d[0]), "+f"(d[1]), "+f"(d[2]), "+f"(d[3])
        : "r"(a[0]), "r"(a[1]), "r"(a[2]), "r"(a[3]), "r"(b[0]), "r"(b[1]));
}
__device__ __forceinline__ void ldsm4(uint32_t* r, uint32_t addr) {
    asm volatile("ldmatrix.sync.aligned.m8n8.x4.shared.b16 {%0,%1,%2,%3}, [%4];"
        : "=r"(r[0]), "=r"(r[1]), "=r"(r[2]), "=r"(r[3]) : "r"(addr));
}
__device__ __forceinline__ uint32_t pack_h2(float2 v) {
    __half2 hh = __floats2half2_rn(v.x, v.y);
    return *reinterpret_cast<uint32_t*>(&hh);
}
// Pack 9-bit candidate index into score mantissa low bits (perturbation <= 2^-14 rel)
__device__ __forceinline__ float packIdx(float s, uint32_t idx) {
    return __uint_as_float((__float_as_uint(s) & 0xFFFFFE00u) | idx);
}

__global__ void __launch_bounds__(NTHREADS, 1) vq_kernel(
    const float* __restrict__ x, const float* __restrict__ emb,
    float* __restrict__ out, int out_size)
{
    extern __shared__ char smem[];
    const uint32_t sb = smem_u32(smem);
    const int tid  = threadIdx.x;
    const int lane = tid & 31;
    const int wid  = tid >> 5;

    // ---- Stage B = fp16(-2e) SW128 + fp32 emb (swizzled) + exact e_sq ----
    if (tid < 512) {
        int r = tid;
        const float4* src = (const float4*)(emb + (size_t)r * DDIM);
        float ssum = 0.f;
#pragma unroll
        for (int j = 0; j < 16; j += 2) {
            float4 v0 = src[j], v1 = src[j + 1];
            ssum = fmaf(v0.x, v0.x, ssum); ssum = fmaf(v0.y, v0.y, ssum);
            ssum = fmaf(v0.z, v0.z, ssum); ssum = fmaf(v0.w, v0.w, ssum);
            ssum = fmaf(v1.x, v1.x, ssum); ssum = fmaf(v1.y, v1.y, ssum);
            ssum = fmaf(v1.z, v1.z, ssum); ssum = fmaf(v1.w, v1.w, ssum);
            *(float4*)(smem + embOff(r, j))     = v0;
            *(float4*)(smem + embOff(r, j + 1)) = v1;
            uint4 hi = make_uint4(
                pack_h2(make_float2(-2.f * v0.x, -2.f * v0.y)),
                pack_h2(make_float2(-2.f * v0.z, -2.f * v0.w)),
                pack_h2(make_float2(-2.f * v1.x, -2.f * v1.y)),
                pack_h2(make_float2(-2.f * v1.z, -2.f * v1.w)));
            uint32_t sw = swz((uint32_t)r * 128u + (uint32_t)(j >> 1) * 16u);
            *(uint4*)(smem + SMEM_B + sw) = hi;
        }
        ((float*)(smem + SMEM_ESQ))[r] = ssum;
    }
    __syncthreads();   // only block-wide barrier in the kernel

    // ---- Per-lane constant B addressing (swizzle algebra hoisted) ----
    const int bRow4 = (lane & 7) + ((lane >> 4) << 3);
    const int bKb4  = ((lane >> 3) & 1) << 4;
    const uint32_t laneBaseB = (uint32_t)bRow4 * 128u + (uint32_t)(bKb4 ^ ((lane & 1) << 4));
    const uint32_t kXor = (uint32_t)(lane & 6) << 4;
    uint32_t bAddr[4];
#pragma unroll
    for (int ks = 0; ks < 4; ks++) {
        bAddr[ks] = sb + SMEM_B + laneBaseB + (((uint32_t)ks * 32u) ^ kXor);
    }

    const float* esq = (const float*)(smem + SMEM_ESQ);
    const int ciB = (lane & 3) * 2;
    const uint32_t idxBase = (uint32_t)(SMEM_IDX + wid * 512);  // warp-private scratch
    const int globalWarp = blockIdx.x * NWARPS_BLK + wid;

    // ---- Fully warp-decoupled chunk loop: 16 rows per warp-chunk ----
    for (int ch = globalWarp; ch < NCHUNKS; ch += NWARPS_TOT) {
        const size_t base = (size_t)ch * 16;

        // ---- A fragments straight from global, fp16 (no bounds: 16 | NROWS) ----
        uint32_t ah[4][4];
        {
            const int kA = (lane & 3) * 2;
            const float* p0 = x + (base + (lane >> 2)) * DDIM + kA;
            const float* p1 = p0 + 8 * DDIM;
#pragma unroll
            for (int ks = 0; ks < 4; ks++) {
                ah[ks][0] = pack_h2(*(const float2*)(p0 + ks * 16));
                ah[ks][1] = pack_h2(*(const float2*)(p1 + ks * 16));
                ah[ks][2] = pack_h2(*(const float2*)(p0 + ks * 16 + 8));
                ah[ks][3] = pack_h2(*(const float2*)(p1 + ks * 16 + 8));
            }
        }

        // ---- Packed top-2 trackers per row-half ----
        float pb1[2], pb2[2];
#pragma unroll
        for (int k = 0; k < 2; k++) { pb1[k] = 3.4e38f; pb2[k] = 3.4e38f; }

        uint32_t nbOff = 0;
        uint32_t id0 = (uint32_t)ciB, id1 = id0 + 1, id2 = id0 + 8, id3 = id0 + 9;

#pragma unroll 1
        for (int np = 0; np < 32; np++) {
            const int nb = np * 16;
            float2 e01 = *(const float2*)(esq + nb + ciB);
            float2 e23 = *(const float2*)(esq + nb + 8 + ciB);
            float acc[2][4];
            acc[0][0] = e01.x; acc[0][1] = e01.y; acc[0][2] = e01.x; acc[0][3] = e01.y;
            acc[1][0] = e23.x; acc[1][1] = e23.y; acc[1][2] = e23.x; acc[1][3] = e23.y;

#pragma unroll
            for (int ks = 0; ks < 4; ks++) {
                uint32_t bh[4];
                ldsm4(bh, bAddr[ks] + nbOff);
                mma_f16(acc[0], ah[ks], bh);
                mma_f16(acc[1], ah[ks], bh + 2);
            }

            // ---- Epilogue: index-packed FMNMX network (validated R13-R16) ----
#pragma unroll
            for (int h = 0; h < 2; h++) {
                float f0 = packIdx(acc[0][h * 2],     id0);
                float f1 = packIdx(acc[0][h * 2 + 1], id1);
                float f2 = packIdx(acc[1][h * 2],     id2);
                float f3 = packIdx(acc[1][h * 2 + 1], id3);
                float lo1 = fminf(f0, f1), hi1 = fmaxf(f0, f1);
                float lo2 = fminf(f2, f3), hi2 = fmaxf(f2, f3);
                float m1 = fminf(lo1, lo2);
                float m2 = fminf(fmaxf(lo1, lo2), fminf(hi1, hi2));
                float tt = fmaxf(pb1[h], m1);
                float uu = fminf(pb2[h], m2);
                pb1[h] = fminf(pb1[h], m1);
                pb2[h] = fminf(tt, uu);
            }
            nbOff += 2048;
            id0 += 16; id1 += 16; id2 += 16; id3 += 16;
        }

        // ---- Write packed top-2 to warp-private scratch: 8 cands per row ----
#pragma unroll
        for (int tk = 0; tk < 2; tk++) {
            int row = tk * 8 + (lane >> 2);
            *(float2*)(smem + idxBase + row * 32 + (lane & 3) * 8) =
                make_float2(pb1[tk], pb2[tk]);
        }
        __syncwarp();

        // ---- Margin-gated winner: lane r (<16) owns row r ----
        int win = 0;
        if (lane < 16) {
            float4 pa = *(const float4*)(smem + idxBase + lane * 32);
            float4 pb = *(const float4*)(smem + idxBase + lane * 32 + 16);
            float loA = fminf(pa.x, pa.y), hiA = fmaxf(pa.x, pa.y);
            float loB = fminf(pa.z, pa.w), hiB = fmaxf(pa.z, pa.w);
            float loC = fminf(pb.x, pb.y), hiC = fmaxf(pb.x, pb.y);
            float loD = fminf(pb.z, pb.w), hiD = fmaxf(pb.z, pb.w);
            float mAB = fminf(loA, loB);
            float sAB = fminf(fmaxf(loA, loB), fminf(hiA, hiB));
            float mCD = fminf(loC, loD);
            float sCD = fminf(fmaxf(loC, loD), fminf(hiC, hiD));
            float m1 = fminf(mAB, mCD);
            float m2 = fminf(fmaxf(mAB, mCD), fminf(sAB, sCD));
            win = (int)(__float_as_uint(m1) & 0x1FFu);
            if (m2 - m1 <= MARGIN) {
                // Exact fp32 rescore of candidates within margin only.
                float v[8] = {pa.x, pa.y, pa.z, pa.w, pb.x, pb.y, pb.z, pb.w};
                const float thr = m1 + MARGIN;
                const float4* xr = (const float4*)(x + (base + lane) * DDIM);
                float best = 3.4e38f; int bidx = 0x7FFFFFFF;
#pragma unroll 1
                for (int i = 0; i < 8; i++) {
                    if (v[i] > thr) continue;
                    int c = (int)(__float_as_uint(v[i]) & 0x1FFu);
                    uint32_t ba = (uint32_t)(SMEM_EMB + c * 256);
                    uint32_t xo = (uint32_t)((c & 7) << 4);
                    float d = 0.f;
#pragma unroll
                    for (int j = 0; j < 16; j++) {
                        float4 xv = xr[j];
                        float4 e = *(const float4*)(smem + ba + (((uint32_t)(j * 16)) ^ xo));
                        float u;
                        u = xv.x - e.x; d = fmaf(u, u, d);
                        u = xv.y - e.y; d = fmaf(u, u, d);
                        u = xv.z - e.z; d = fmaf(u, u, d);
                        u = xv.w - e.w; d = fmaf(u, u, d);
                    }
                    if (d < best || (d == best && c < bidx)) { best = d; bidx = c; }
                }
                win = bidx;
            }
            if (out_size >= NROWS * DDIM + NROWS) {
                out[(size_t)NROWS * DDIM + base + lane] = (float)win;
            }
        }

        // ---- Gather quantized rows: winner via shuffle, 16 lanes per row ----
        if (out_size >= NROWS * DDIM) {
            const int jj = lane & 15;
#pragma unroll
            for (int sweep = 0; sweep < 8; sweep++) {
                int r = sweep * 2 + (lane >> 4);
                int w = __shfl_sync(0xFFFFFFFFu, win, r);
                float4 v = *(const float4*)(smem + embOff(w, jj));
                ((float4*)(out + (base + r) * DDIM))[jj] = v;
            }
        }
        __syncwarp();   // protect warp-private IDX before next chunk's writes
    }
}

extern "C" void kernel_launch(void* const* d_in, const int* in_sizes, int n_in,
                              void* d_out, int out_size) {
    const float* x   = (const float*)d_in[0];
    const float* emb = (const float*)d_in[1];
    float* out = (float*)d_out;
    cudaFuncSetAttribute(vq_kernel, cudaFuncAttributeMaxDynamicSharedMemorySize, SMEM_TOTAL);
    vq_kernel<<<NBLOCKS, NTHREADS, SMEM_TOTAL>>>(x, emb, out, out_size);
}